// round 4
// baseline (speedup 1.0000x reference)
#include <cuda_runtime.h>

// Problem constants (fixed by the dataset)
#define TT 512
#define BB 32
#define NN 64
#define KK 32
#define DD 2
#define SAMP_PER_B (TT * NN)          // 32768 samples per batch element
#define SLICES 64                     // CTAs per batch along the sample axis
#define SAMP_PER_CTA (SAMP_PER_B / SLICES)  // 512
#define CHUNK 32
#define NCHUNK (SAMP_PER_CTA / CHUNK)       // 16
#define U_BLOCKS 256

// Deterministic scratch (no device allocation allowed)
__device__ float g_part[BB * SLICES * 2 * 1024];   // 16 MB, fully overwritten each launch
__device__ float g_berg[BB];
__device__ float g_upart[U_BLOCKS];

// ---- packed f32x2 helpers (Blackwell FFMA2) ----
__device__ __forceinline__ double ffma2(double a, double b, double c) {
    double d;
    asm("fma.rn.f32x2 %0, %1, %2, %3;" : "=d"(d) : "d"(a), "d"(b), "d"(c));
    return d;
}
__device__ __forceinline__ double packdup(float a) {
    double d;
    asm("mov.b64 %0, {%1, %2};" : "=d"(d) : "f"(a), "f"(a));
    return d;
}
__device__ __forceinline__ float2 unpack2(double d) {
    float2 r;
    asm("mov.b64 {%0, %1}, %2;" : "=f"(r.x), "=f"(r.y) : "d"(d));
    return r;
}

// ============================================================================
// Pass 1: per-(batch, slice) partial S accumulation.
// 64 threads/CTA. Each chunk: 32 samples' cos tables generated into smem
// (1 thread per sample-dim, Chebyshev recurrence), then consumed as a
// 32x32 += [32x32]^T [32x32] outer-product accumulation with 4x8 register
// tiles in packed f32x2. Two half-warps interleave on the sample (K) axis and
// write separate partials (summed deterministically in pass 2).
// ============================================================================
__global__ void __launch_bounds__(64, 16)
pass1_kernel(const float* __restrict__ x, const float* __restrict__ L) {
    __shared__ float sA[CHUNK][36];   // c0: rows = sample, cols = mode p (pad 36 floats: 16B-aligned rows, 2-way max conflict)
    __shared__ float sB[CHUNK][36];   // c1

    const int slice = blockIdx.x;
    const int b     = blockIdx.y;
    const int tid   = threadIdx.x;

    // --- generation role: thread g handles sample (g>>1), dim (g&1) ---
    const int   gs   = tid >> 1;
    const int   gdim = tid & 1;
    const float invL = 3.14159265358979323846f / __ldg(&L[gdim]);
    float* grow = gdim ? &sB[gs][0] : &sA[gs][0];

    // --- consumer role: lane covers a 4(p) x 8(q) tile; half = sample parity ---
    const int lane = tid & 31;
    const int half = tid >> 5;
    const int pg   = lane >> 2;   // 0..7 -> rows 4*pg..4*pg+3
    const int qg   = lane & 3;    // 0..3 -> cols 8*qg..8*qg+7

    double acc[4][4];
#pragma unroll
    for (int i = 0; i < 4; i++)
#pragma unroll
        for (int j = 0; j < 4; j++) acc[i][j] = 0.0;

    const int sbase = slice * SAMP_PER_CTA;

    for (int chunk = 0; chunk < NCHUNK; chunk++) {
        // ---- generate cos tables for 32 samples ----
        {
            const int sidx = sbase + chunk * CHUNK + gs;
            const int t = sidx >> 6;          // / NN
            const int n = sidx & (NN - 1);
            const float xv = x[((t * BB + b) * NN + n) * DD + gdim];
            const float cv = __cosf(xv * invL);
            const float c2 = 2.0f * cv;
            float v0 = 1.0f, v1 = cv;
#pragma unroll
            for (int j = 0; j < 8; j++) {
                float4 o;
                o.x = v0; o.y = v1;
                const float v2 = fmaf(c2, v1, -v0);
                const float v3 = fmaf(c2, v2, -v1);
                o.z = v2; o.w = v3;
                v0 = fmaf(c2, v3, -v2);
                v1 = fmaf(c2, v0, -v3);
                *reinterpret_cast<float4*>(&grow[4 * j]) = o;
            }
        }
        __syncthreads();

        // ---- consume: 16 sample-steps per half-warp ----
#pragma unroll
        for (int ss = 0; ss < CHUNK / 2; ss++) {
            const int s = ss * 2 + half;
            const float4  a   = *reinterpret_cast<const float4*>(&sA[s][pg * 4]);
            const double2 bb0 = *reinterpret_cast<const double2*>(&sB[s][qg * 8]);
            const double2 bb1 = *reinterpret_cast<const double2*>(&sB[s][qg * 8 + 4]);
            double aa;
            aa = packdup(a.x);
            acc[0][0] = ffma2(aa, bb0.x, acc[0][0]);
            acc[0][1] = ffma2(aa, bb0.y, acc[0][1]);
            acc[0][2] = ffma2(aa, bb1.x, acc[0][2]);
            acc[0][3] = ffma2(aa, bb1.y, acc[0][3]);
            aa = packdup(a.y);
            acc[1][0] = ffma2(aa, bb0.x, acc[1][0]);
            acc[1][1] = ffma2(aa, bb0.y, acc[1][1]);
            acc[1][2] = ffma2(aa, bb1.x, acc[1][2]);
            acc[1][3] = ffma2(aa, bb1.y, acc[1][3]);
            aa = packdup(a.z);
            acc[2][0] = ffma2(aa, bb0.x, acc[2][0]);
            acc[2][1] = ffma2(aa, bb0.y, acc[2][1]);
            acc[2][2] = ffma2(aa, bb1.x, acc[2][2]);
            acc[2][3] = ffma2(aa, bb1.y, acc[2][3]);
            aa = packdup(a.w);
            acc[3][0] = ffma2(aa, bb0.x, acc[3][0]);
            acc[3][1] = ffma2(aa, bb0.y, acc[3][1]);
            acc[3][2] = ffma2(aa, bb1.x, acc[3][2]);
            acc[3][3] = ffma2(aa, bb1.y, acc[3][3]);
        }
        __syncthreads();
    }

    // ---- write partial tile to scratch ----
    float* dst = g_part + (((size_t)b * SLICES + slice) * 2 + half) * 1024;
#pragma unroll
    for (int i = 0; i < 4; i++) {
        const int p = pg * 4 + i;
#pragma unroll
        for (int j = 0; j < 4; j++) {
            const float2 v = unpack2(acc[i][j]);
            const int q = qg * 8 + 2 * j;
            dst[p * KK + q]     = v.x;
            dst[p * KK + q + 1] = v.y;
        }
    }
}

// ============================================================================
// Pass 2a: per-batch weighted squared-error reduction over the 32x32 modes.
// ============================================================================
__global__ void pass2_kernel(const float* __restrict__ cd,
                             const float* __restrict__ nf,
                             const float* __restrict__ nw) {
    const int b   = blockIdx.x;
    const int tid = threadIdx.x;   // 1024: tid = p*32+q
    float s = 0.0f;
    const float* base = g_part + (size_t)b * SLICES * 2 * 1024 + tid;
#pragma unroll 8
    for (int i = 0; i < SLICES * 2; i++) s += base[i * 1024];
    const float coeff = s / (nf[tid] * (float)SAMP_PER_B);
    const float diff  = coeff - cd[tid];
    float term = diff * diff * nw[tid];

    __shared__ float red[1024];
    red[tid] = term;
    __syncthreads();
    for (int off = 512; off > 0; off >>= 1) {
        if (tid < off) red[tid] += red[tid + off];
        __syncthreads();
    }
    if (tid == 0) g_berg[b] = red[0];
}

// ============================================================================
// Pass 2b: |u|^2 partial sums (deterministic fixed-stride assignment).
// ============================================================================
__global__ void usum_kernel(const float4* __restrict__ u4, int n4) {
    const int tid = threadIdx.x;
    const int blk = blockIdx.x;
    float s = 0.0f;
    for (int i = blk * 256 + tid; i < n4; i += U_BLOCKS * 256) {
        const float4 v = u4[i];
        s = fmaf(v.x, v.x, s);
        s = fmaf(v.y, v.y, s);
        s = fmaf(v.z, v.z, s);
        s = fmaf(v.w, v.w, s);
    }
    __shared__ float red[256];
    red[tid] = s;
    __syncthreads();
    for (int off = 128; off > 0; off >>= 1) {
        if (tid < off) red[tid] += red[tid + off];
        __syncthreads();
    }
    if (tid == 0) g_upart[blk] = red[0];
}

// ============================================================================
// Pass 3: final combine.
// ============================================================================
__global__ void final_kernel(float* __restrict__ out) {
    const int tid = threadIdx.x;   // 256
    const float UC = 1.0e-3f / (2.0f * (float)SAMP_PER_B * (float)BB);
    float v = g_upart[tid] * UC;
    if (tid < BB) v += g_berg[tid];
    __shared__ float red[256];
    red[tid] = v;
    __syncthreads();
    for (int off = 128; off > 0; off >>= 1) {
        if (tid < off) red[tid] += red[tid + off];
        __syncthreads();
    }
    if (tid == 0) out[0] = red[0];
}

// ============================================================================
// Launch
// ============================================================================
extern "C" void kernel_launch(void* const* d_in, const int* in_sizes, int n_in,
                              void* d_out, int out_size) {
    const float* x  = (const float*)d_in[0];
    const float* u  = (const float*)d_in[1];
    const float* L  = (const float*)d_in[2];
    const float* cd = (const float*)d_in[3];
    const float* nf = (const float*)d_in[4];
    const float* nw = (const float*)d_in[5];
    float* out = (float*)d_out;

    const int n_u = in_sizes[1];          // T*B*N*2 = 2,097,152

    dim3 grid1(SLICES, BB);
    pass1_kernel<<<grid1, 64>>>(x, L);
    usum_kernel<<<U_BLOCKS, 256>>>((const float4*)u, n_u / 4);
    pass2_kernel<<<BB, 1024>>>(cd, nf, nw);
    final_kernel<<<1, 256>>>(out);
}